// round 15
// baseline (speedup 1.0000x reference)
#include <cuda_runtime.h>
#include <cuda_bf16.h>
#include <stdint.h>
#include <math.h>

#define NN 4096
#define EE_MAX 131072
#define EPMAX (EE_MAX + NN)
#define INC 512
#define NHEADS 8
#define HID 64
#define OUTC 256
#define WORDS (NN / 32)
#define NEG 0.2f
#define MAXDEG 384
#define HP 9   // padded head stride (conflict-free smem)

// ------------------------- device scratch (static, no allocs) ---------------
__device__ int g_src[EE_MAX], g_dst[EE_MAX];
__device__ __align__(16) unsigned g_adj[NN * WORDS];   // zero at load; re-zeroed by sma2 tail
__device__ int g_deg[NN];
__device__ int g_rowptr[NN + 1];
__device__ int g_cols[EPMAX];
__device__ float g_d1[NN], g_d2[NN], g_d3[NN];
__device__ __align__(16) unsigned short g_A2h[NN * NN];   // 32 MB dense A@A (u16)
__device__ float g_h1[NN * INC];
__device__ float g_h2w[NN * OUTC];
__device__ float g_s1s[NN * NHEADS], g_s1d[NN * NHEADS];
__device__ float g_s2s[NN], g_s2d[NN];   // accumulated by gemm23 epilogue; zeroed in dualscan
__device__ __align__(16) int g_hist[NN];               // zero at load; re-zeroed by sma2 tail
__device__ int g_dptr[NN + 1];
__device__ int g_dcur[NN];
__device__ int g_esrc[EPMAX];            // src node per CSR position (coalesced)
__device__ int g_edst[EPMAX];            // dst node per CSR position
__device__ float g_mwq[EPMAX];           // motif weight per CSR position (coalesced)

// bf16 split operands (hi + lo)
__device__ __align__(16) __nv_bfloat16 g_xhi[NN * INC], g_xlo[NN * INC];
__device__ __align__(16) __nv_bfloat16 g_w1hi[INC * INC], g_w1lo[INC * INC];
__device__ __align__(16) __nv_bfloat16 g_w2hi[INC * OUTC], g_w2lo[INC * OUTC];
__device__ __align__(16) __nv_bfloat16 g_rwhi[INC * OUTC], g_rwlo[INC * OUTC];
__device__ __align__(16) __nv_bfloat16 g_h2hi[NN * INC], g_h2lo[NN * INC];

// ------------------ convert + bitmap + hist (pre-zeroed) ---------------------
__global__ void k_convert(const void* p, int E) {
    __shared__ int any;
    if (threadIdx.x == 0) any = 0;
    __syncthreads();
    const int* w = (const int*)p;
#pragma unroll
    for (int t = 0; t < 4; t++) {
        int idx = threadIdx.x + t * 256;
        if (w[2 * idx + 1] != 0) any = 1;
    }
    __syncthreads();
    bool is64 = (any == 0);
    int i = blockIdx.x * blockDim.x + threadIdx.x;
    int EP = E + NN;
    if (i >= EP) return;
    int s, d;
    if (i < E) {
        if (is64) {
            const long long* q = (const long long*)p;
            s = (int)q[i];
            d = (int)q[E + i];
        } else {
            const int* q = (const int*)p;
            s = q[i];
            d = q[E + i];
        }
        g_src[i] = s;
        g_dst[i] = d;
    } else {
        s = i - E;
        d = i - E;
    }
    atomicOr(&g_adj[s * WORDS + (d >> 5)], 1u << (d & 31));
    atomicAdd(&g_hist[d], 1);
}

// ------------------------- fp32 -> (hi,lo) bf16 split ------------------------
__device__ __forceinline__ void split8(const float* __restrict__ src,
                                       __nv_bfloat16* __restrict__ hi,
                                       __nv_bfloat16* __restrict__ lo, int i) {
    const float4* s4 = (const float4*)src;
    float4 v0 = s4[2 * i], v1 = s4[2 * i + 1];
    float f[8] = {v0.x, v0.y, v0.z, v0.w, v1.x, v1.y, v1.z, v1.w};
    __nv_bfloat16 h[8], l[8];
#pragma unroll
    for (int k = 0; k < 8; k++) {
        h[k] = __float2bfloat16(f[k]);
        l[k] = __float2bfloat16(f[k] - __bfloat162float(h[k]));
    }
    ((uint4*)hi)[i] = *(uint4*)h;
    ((uint4*)lo)[i] = *(uint4*)l;
}

#define NX8 (NN * INC / 8)
#define NW18 (INC * INC / 8)
#define NW28 (INC * OUTC / 8)
__global__ void k_splitall(const float* __restrict__ x, const float* __restrict__ W1,
                           const float* __restrict__ W2, const float* __restrict__ rW2) {
    int i = blockIdx.x * blockDim.x + threadIdx.x;
    if (i < NX8) { split8(x, g_xhi, g_xlo, i); return; }
    i -= NX8;
    if (i < NW18) { split8(W1, g_w1hi, g_w1lo, i); return; }
    i -= NW18;
    if (i < NW28) { split8(W2, g_w2hi, g_w2lo, i); return; }
    i -= NW28;
    if (i < NW28) { split8(rW2, g_rwhi, g_rwlo, i); return; }
}

// ------------------------- degree / scans / build ----------------------------
__global__ void k_deg() {
    int r = blockIdx.x * blockDim.x + threadIdx.x;
    if (r >= NN) return;
    const uint4* row = (const uint4*)(g_adj + r * WORDS);
    int c = 0;
#pragma unroll
    for (int w = 0; w < WORDS / 4; w++) {
        uint4 v = row[w];
        c += __popc(v.x) + __popc(v.y) + __popc(v.z) + __popc(v.w);
    }
    g_deg[r] = c;
    g_d1[r] = (float)c;
}

__global__ void k_dualscan() {
    __shared__ int s[1024];
    int tid = threadIdx.x;
#pragma unroll
    for (int pass = 0; pass < 2; pass++) {
        const int* in = pass ? g_hist : g_deg;
        int* out = pass ? g_dptr : g_rowptr;
        int base = tid * 4;
        int loc[4];
        int tot = 0;
#pragma unroll
        for (int i = 0; i < 4; i++) { loc[i] = tot; tot += in[base + i]; }
        s[tid] = tot;
        __syncthreads();
        for (int off = 1; off < 1024; off <<= 1) {
            int t = (tid >= off) ? s[tid - off] : 0;
            __syncthreads();
            s[tid] += t;
            __syncthreads();
        }
        int pre = (tid == 0) ? 0 : s[tid - 1];
#pragma unroll
        for (int i = 0; i < 4; i++) {
            out[base + i] = pre + loc[i];
            if (pass) g_dcur[base + i] = pre + loc[i];
        }
        if (tid == 1023) out[4096] = s[1023];
        __syncthreads();
    }
    // zero the s2 score accumulators (consumed by next gemm23 epilogue)
    int b4 = tid * 4;
#pragma unroll
    for (int i = 0; i < 4; i++) {
        g_s2s[b4 + i] = 0.f;
        g_s2d[b4 + i] = 0.f;
    }
}

__global__ void k_build(int E) {
    int EP = E + NN;
    if (blockIdx.x < 16) {
        int r = blockIdx.x * blockDim.x + threadIdx.x;
        if (r >= NN) return;
        int p = g_rowptr[r];
        float d2 = 0.f;
        for (int w = 0; w < WORDS; w++) {
            unsigned m = g_adj[r * WORDS + w];
            while (m) {
                int b = __ffs(m) - 1;
                int c = w * 32 + b;
                g_cols[p++] = c;
                d2 += g_d1[c];
                m &= m - 1;
            }
        }
        g_d2[r] = d2;
    } else {
        int e = (blockIdx.x - 16) * blockDim.x + threadIdx.x;
        if (e >= EP) return;
        int s, d;
        if (e < E) { s = g_src[e]; d = g_dst[e]; }
        else { s = e - E; d = e - E; }
        int pos = atomicAdd(&g_dcur[d], 1);
        g_esrc[pos] = s;
        g_edst[pos] = d;
    }
}

// ------------- A2 row in shared memory + d3[k] = A*d2 ------------------------
__global__ void __launch_bounds__(256) k_a2() {
    __shared__ unsigned short row[NN];
    int tid = threadIdx.x;
    unsigned* roww = (unsigned*)row;
    for (int i = tid; i < NN / 2; i += 256) roww[i] = 0u;
    __syncthreads();
    int k = blockIdx.x;
    int p0 = g_rowptr[k], p1 = g_rowptr[k + 1];
    float d3 = 0.f;
    for (int i = p0 + tid; i < p1; i += 256) d3 += g_d2[g_cols[i]];
    for (int o = 16; o; o >>= 1) d3 += __shfl_xor_sync(0xffffffffu, d3, o);
    __shared__ float sred[8];
    if ((tid & 31) == 0) sred[tid >> 5] = d3;
    int wid = tid >> 5, lane = tid & 31;
    for (int mi = p0 + wid; mi < p1; mi += 8) {
        int m = g_cols[mi];
        int q1 = g_rowptr[m + 1];
        for (int j = g_rowptr[m] + lane; j < q1; j += 32) {
            int d = g_cols[j];
            atomicAdd(&roww[d >> 1], (d & 1) ? 0x10000u : 1u);
        }
    }
    __syncthreads();
    if (tid == 0) {
        float t = 0.f;
        for (int i = 0; i < 8; i++) t += sred[i];
        g_d3[k] = t;
    }
    uint4* dst = (uint4*)(g_A2h + (size_t)k * NN);
    const uint4* srcv = (const uint4*)row;
    for (int i = tid; i < NN / 8; i += 256) dst[i] = srcv[i];
}

// mw per CSR position (coalesced output for the sma kernels)
__global__ void k_mw(int E) {
    int pos = blockIdx.x * blockDim.x + threadIdx.x;
    int EP = E + NN;
    if (pos >= EP) return;
    int s = g_esrc[pos];
    int d = g_edst[pos];
    float a3 = 0.f;
    int p1 = g_rowptr[s + 1];
    for (int i = g_rowptr[s]; i < p1; i++)
        a3 += (float)g_A2h[(size_t)g_cols[i] * NN + d];
    float nm = g_d3[s];
    if (nm < 1.f) nm = 1.f;
    g_mwq[pos] = a3 / nm;
}

// ------------------------- split-bf16 HMMA GEMM ------------------------------
#define PAD_A 40
#define PITCH_B 136

__device__ __forceinline__ void mma_bf16(float* c, const unsigned* a, const unsigned* b) {
    asm volatile(
        "mma.sync.aligned.m16n8k16.row.col.f32.bf16.bf16.f32 "
        "{%0,%1,%2,%3}, {%4,%5,%6,%7}, {%8,%9}, {%0,%1,%2,%3};"
        : "+f"(c[0]), "+f"(c[1]), "+f"(c[2]), "+f"(c[3])
        : "r"(a[0]), "r"(a[1]), "r"(a[2]), "r"(a[3]), "r"(b[0]), "r"(b[1]));
}

template <bool FUSE_S2>
__device__ __forceinline__ void gemm_split(const __nv_bfloat16* __restrict__ Ahi,
                                           const __nv_bfloat16* __restrict__ Alo,
                                           const __nv_bfloat16* __restrict__ Bhi,
                                           const __nv_bfloat16* __restrict__ Blo,
                                           int ldb, int col0,
                                           float* __restrict__ C, int ldc, int row0,
                                           const float* __restrict__ av,
                                           const float* __restrict__ dv) {
    __shared__ __nv_bfloat16 As[2][128 * PAD_A];
    __shared__ __nv_bfloat16 Bs[2][32 * PITCH_B];
    int tid = threadIdx.x;
    int wid = tid >> 5, lane = tid & 31;
    int wm = (wid >> 2) * 64;
    int wn = (wid & 3) * 32;
    int g = lane >> 2, q = lane & 3;
    float acc[4][4][4] = {};

    for (int k0 = 0; k0 < INC; k0 += 32) {
#pragma unroll
        for (int l = 0; l < 2; l++) {
            int slot = tid + l * 256;
            int r = slot >> 2, cg = (slot & 3) << 3;
            *(float4*)&As[0][r * PAD_A + cg] = *(const float4*)&Ahi[(row0 + r) * INC + k0 + cg];
            *(float4*)&As[1][r * PAD_A + cg] = *(const float4*)&Alo[(row0 + r) * INC + k0 + cg];
        }
#pragma unroll
        for (int l = 0; l < 2; l++) {
            int slot = tid + l * 256;
            int kr = slot >> 4, ng = (slot & 15) << 3;
            *(float4*)&Bs[0][kr * PITCH_B + ng] = *(const float4*)&Bhi[(k0 + kr) * ldb + col0 + ng];
            *(float4*)&Bs[1][kr * PITCH_B + ng] = *(const float4*)&Blo[(k0 + kr) * ldb + col0 + ng];
        }
        __syncthreads();
#pragma unroll
        for (int ks = 0; ks < 2; ks++) {
            int kb = ks * 16;
            unsigned ah[4][4], al[4][4], bh[4][2], bl[4][2];
#pragma unroll
            for (int i = 0; i < 4; i++) {
                int m = wm + i * 16 + g;
                int o0 = m * PAD_A + kb + q * 2;
                int o1 = (m + 8) * PAD_A + kb + q * 2;
                ah[i][0] = *(const unsigned*)&As[0][o0];
                ah[i][1] = *(const unsigned*)&As[0][o1];
                ah[i][2] = *(const unsigned*)&As[0][o0 + 8];
                ah[i][3] = *(const unsigned*)&As[0][o1 + 8];
                al[i][0] = *(const unsigned*)&As[1][o0];
                al[i][1] = *(const unsigned*)&As[1][o1];
                al[i][2] = *(const unsigned*)&As[1][o0 + 8];
                al[i][3] = *(const unsigned*)&As[1][o1 + 8];
            }
#pragma unroll
            for (int j = 0; j < 4; j++) {
                int n = wn + j * 8 + g;
                int k2 = kb + q * 2;
#pragma unroll
                for (int t = 0; t < 2; t++) {
                    int kk = k2 + t * 8;
                    unsigned h0 = *(const unsigned short*)&Bs[0][kk * PITCH_B + n];
                    unsigned h1 = *(const unsigned short*)&Bs[0][(kk + 1) * PITCH_B + n];
                    bh[j][t] = h0 | (h1 << 16);
                    unsigned l0 = *(const unsigned short*)&Bs[1][kk * PITCH_B + n];
                    unsigned l1 = *(const unsigned short*)&Bs[1][(kk + 1) * PITCH_B + n];
                    bl[j][t] = l0 | (l1 << 16);
                }
            }
#pragma unroll
            for (int i = 0; i < 4; i++)
#pragma unroll
                for (int j = 0; j < 4; j++) {
                    mma_bf16(acc[i][j], ah[i], bh[j]);
                    mma_bf16(acc[i][j], ah[i], bl[j]);
                    mma_bf16(acc[i][j], al[i], bh[j]);
                }
        }
        __syncthreads();
    }
#pragma unroll
    for (int i = 0; i < 4; i++)
#pragma unroll
        for (int j = 0; j < 4; j++) {
            int r = row0 + wm + i * 16 + g;
            int c = col0 + wn + j * 8 + q * 2;
            C[r * ldc + c] = acc[i][j][0];
            C[r * ldc + c + 1] = acc[i][j][1];
            C[(r + 8) * ldc + c] = acc[i][j][2];
            C[(r + 8) * ldc + c + 1] = acc[i][j][3];
        }
    if (FUSE_S2) {
#pragma unroll
        for (int i = 0; i < 4; i++) {
            float s0 = 0.f, d0 = 0.f, s8 = 0.f, d8 = 0.f;
#pragma unroll
            for (int j = 0; j < 4; j++) {
                int c = col0 + wn + j * 8 + q * 2;
                float a0 = av[c], a1 = av[c + 1];
                float e0 = dv[c], e1 = dv[c + 1];
                s0 += acc[i][j][0] * a0 + acc[i][j][1] * a1;
                d0 += acc[i][j][0] * e0 + acc[i][j][1] * e1;
                s8 += acc[i][j][2] * a0 + acc[i][j][3] * a1;
                d8 += acc[i][j][2] * e0 + acc[i][j][3] * e1;
            }
            s0 += __shfl_xor_sync(0xffffffffu, s0, 1);
            s0 += __shfl_xor_sync(0xffffffffu, s0, 2);
            d0 += __shfl_xor_sync(0xffffffffu, d0, 1);
            d0 += __shfl_xor_sync(0xffffffffu, d0, 2);
            s8 += __shfl_xor_sync(0xffffffffu, s8, 1);
            s8 += __shfl_xor_sync(0xffffffffu, s8, 2);
            d8 += __shfl_xor_sync(0xffffffffu, d8, 1);
            d8 += __shfl_xor_sync(0xffffffffu, d8, 2);
            if (q == 0) {
                int r = row0 + wm + i * 16 + g;
                atomicAdd(&g_s2s[r], s0);
                atomicAdd(&g_s2d[r], d0);
                atomicAdd(&g_s2s[r + 8], s8);
                atomicAdd(&g_s2d[r + 8], d8);
            }
        }
    }
}

__global__ void __launch_bounds__(256) k_gemm1() {
    gemm_split<false>(g_xhi, g_xlo, g_w1hi, g_w1lo, INC, blockIdx.x * 128, g_h1, INC,
                      blockIdx.y * 128, 0, 0);
}

__global__ void __launch_bounds__(256) k_gemm23(float* __restrict__ out,
                                                const float* __restrict__ as2,
                                                const float* __restrict__ ad2) {
    int bx = blockIdx.x;
    if (bx < 2) {
        gemm_split<true>(g_h2hi, g_h2lo, g_w2hi, g_w2lo, OUTC, (bx & 1) * 128,
                         g_h2w, OUTC, blockIdx.y * 128, as2, ad2);
    } else {
        gemm_split<false>(g_h2hi, g_h2lo, g_rwhi, g_rwlo, OUTC, (bx & 1) * 128,
                          out, OUTC, blockIdx.y * 128, 0, 0);
    }
}

// ------------------- attention scores (layer 1) ------------------------------
__global__ void k_s1(const float* __restrict__ as1, const float* __restrict__ ad1) {
    int n = blockIdx.x;
    int h = threadIdx.x >> 5, lane = threadIdx.x & 31;
    float2 v = *(const float2*)&g_h1[n * INC + h * HID + lane * 2];
    float2 a = *(const float2*)&as1[h * HID + lane * 2];
    float2 d = *(const float2*)&ad1[h * HID + lane * 2];
    float ss = v.x * a.x + v.y * a.y;
    float sd = v.x * d.x + v.y * d.y;
    for (int o = 16; o; o >>= 1) {
        ss += __shfl_xor_sync(0xffffffffu, ss, o);
        sd += __shfl_xor_sync(0xffffffffu, sd, o);
    }
    if (lane == 0) {
        g_s1s[n * NHEADS + h] = ss;
        g_s1d[n * NHEADS + h] = sd;
    }
}

// ---- fused softmax + aggregate + split, layer 1 (single gather pass) --------
__device__ __forceinline__ float lrelu(float x) { return x > 0.f ? x : NEG * x; }

__global__ void __launch_bounds__(256) k_sma1(const float* __restrict__ b1, int E) {
    __shared__ float sl1[MAXDEG * HP];    // lrelu(ev)         13.8 KB
    __shared__ float sl2[MAXDEG * HP];    // lrelu(ev*mw)      13.8 KB
    __shared__ float sal[MAXDEG * HP];    // alphas            13.8 KB
    __shared__ int se[MAXDEG];
    __shared__ float sm1[NHEADS], sr1[NHEADS], sm2[NHEADS], sr2[NHEADS];
    int n = blockIdx.x;
    int p0 = g_dptr[n], p1 = g_dptr[n + 1];
    int cnt = p1 - p0;
    int tid = threadIdx.x, h = tid >> 5, lane = tid & 31;
    float sd = g_s1d[n * NHEADS + h];
    float m1 = -1e30f, m2 = -1e30f;
    // pass 1: gather once, materialize l1/l2, track maxima
    for (int i = lane; i < cnt; i += 32) {
        int s = g_esrc[p0 + i];
        if (h == 0 && i < MAXDEG) se[i] = s;
        float ev = g_s1s[s * NHEADS + h] + sd;
        float l1 = lrelu(ev);
        float l2 = lrelu(ev * g_mwq[p0 + i]);
        if (i < MAXDEG) { sl1[i * HP + h] = l1; sl2[i * HP + h] = l2; }
        m1 = fmaxf(m1, l1);
        m2 = fmaxf(m2, l2);
    }
    for (int o = 16; o; o >>= 1) {
        m1 = fmaxf(m1, __shfl_xor_sync(0xffffffffu, m1, o));
        m2 = fmaxf(m2, __shfl_xor_sync(0xffffffffu, m2, o));
    }
    // pass 2: sums from smem
    float s1 = 0.f, s2 = 0.f;
    for (int i = lane; i < cnt; i += 32) {
        float l1, l2;
        if (i < MAXDEG) {
            l1 = sl1[i * HP + h];
            l2 = sl2[i * HP + h];
        } else {
            int s = g_esrc[p0 + i];
            float ev = g_s1s[s * NHEADS + h] + sd;
            l1 = lrelu(ev);
            l2 = lrelu(ev * g_mwq[p0 + i]);
        }
        s1 += expf(l1 - m1);
        s2 += expf(l2 - m2);
    }
    for (int o = 16; o; o >>= 1) {
        s1 += __shfl_xor_sync(0xffffffffu, s1, o);
        s2 += __shfl_xor_sync(0xffffffffu, s2, o);
    }
    float r1 = 0.5f / (s1 + 1e-16f);
    float r2 = 0.5f / (s2 + 1e-16f);
    // pass 3: alphas from smem
    for (int i = lane; i < cnt && i < MAXDEG; i += 32)
        sal[i * HP + h] = expf(sl1[i * HP + h] - m1) * r1
                        + expf(sl2[i * HP + h] - m2) * r2;
    if (lane == 0) { sm1[h] = m1; sr1[h] = r1; sm2[h] = m2; sr2[h] = r2; }
    __syncthreads();
    // aggregation: warp h handles channels [h*64, h*64+63]
    int c = h * HID + lane * 2;
    float2 acc = make_float2(0.f, 0.f);
    for (int i = 0; i < cnt; i++) {
        float a;
        int s;
        if (i < MAXDEG) {
            s = se[i];
            a = sal[i * HP + h];
        } else {
            s = g_esrc[p0 + i];
            float ev = g_s1s[s * NHEADS + h] + sd;
            a = expf(lrelu(ev) - sm1[h]) * sr1[h]
              + expf(lrelu(ev * g_mwq[p0 + i]) - sm2[h]) * sr2[h];
        }
        float2 v = *(const float2*)&g_h1[s * INC + c];
        acc.x += a * v.x;
        acc.y += a * v.y;
    }
    float2 bb = *(const float2*)&b1[c];
    float rx = acc.x + bb.x, ry = acc.y + bb.y;
    rx = rx > 0.f ? rx : expm1f(rx);
    ry = ry > 0.f ? ry : expm1f(ry);
    __nv_bfloat16 hx = __float2bfloat16(rx);
    __nv_bfloat16 hy = __float2bfloat16(ry);
    __nv_bfloat16 lx = __float2bfloat16(rx - __bfloat162float(hx));
    __nv_bfloat16 ly = __float2bfloat16(ry - __bfloat162float(hy));
    __nv_bfloat162 hp; hp.x = hx; hp.y = hy;
    __nv_bfloat162 lp; lp.x = lx; lp.y = ly;
    *(__nv_bfloat162*)&g_h2hi[n * INC + c] = hp;
    *(__nv_bfloat162*)&g_h2lo[n * INC + c] = lp;
}

// ------ fused softmax + aggregate, layer 2 (single gather pass + cleanup) ----
__global__ void __launch_bounds__(256) k_sma2(const float* __restrict__ b2,
                                              float* __restrict__ out, int E) {
    int n = blockIdx.x;
    if (n >= NN) {   // cleanup blocks: re-zero adj + hist for the next launch
        int idx = (n - NN) * 256 + threadIdx.x;
        uint4 zu = make_uint4(0u, 0u, 0u, 0u);
        uint4* adjv = (uint4*)g_adj;
        for (int i = idx; i < NN * WORDS / 4; i += 64 * 256) adjv[i] = zu;
        uint4* hv = (uint4*)g_hist;
        for (int i = idx; i < NN / 4; i += 64 * 256) hv[i] = zu;
        return;
    }
    __shared__ float sl1[MAXDEG];
    __shared__ float sl2[MAXDEG];
    __shared__ float sal[MAXDEG];
    __shared__ int se[MAXDEG];
    __shared__ float st[4];
    int p0 = g_dptr[n], p1 = g_dptr[n + 1];
    int cnt = p1 - p0;
    int tid = threadIdx.x;
    if (tid < 32) {
        int lane = tid;
        float sd = g_s2d[n];
        float m1 = -1e30f, m2 = -1e30f;
        for (int i = lane; i < cnt; i += 32) {
            int s = g_esrc[p0 + i];
            if (i < MAXDEG) se[i] = s;
            float ev = g_s2s[s] + sd;
            float l1 = lrelu(ev);
            float l2 = lrelu(ev * g_mwq[p0 + i]);
            if (i < MAXDEG) { sl1[i] = l1; sl2[i] = l2; }
            m1 = fmaxf(m1, l1);
            m2 = fmaxf(m2, l2);
        }
        for (int o = 16; o; o >>= 1) {
            m1 = fmaxf(m1, __shfl_xor_sync(0xffffffffu, m1, o));
            m2 = fmaxf(m2, __shfl_xor_sync(0xffffffffu, m2, o));
        }
        float s1 = 0.f, s2 = 0.f;
        for (int i = lane; i < cnt; i += 32) {
            float l1, l2;
            if (i < MAXDEG) { l1 = sl1[i]; l2 = sl2[i]; }
            else {
                int s = g_esrc[p0 + i];
                float ev = g_s2s[s] + sd;
                l1 = lrelu(ev);
                l2 = lrelu(ev * g_mwq[p0 + i]);
            }
            s1 += expf(l1 - m1);
            s2 += expf(l2 - m2);
        }
        for (int o = 16; o; o >>= 1) {
            s1 += __shfl_xor_sync(0xffffffffu, s1, o);
            s2 += __shfl_xor_sync(0xffffffffu, s2, o);
        }
        float r1 = 0.5f / (s1 + 1e-16f);
        float r2 = 0.5f / (s2 + 1e-16f);
        for (int i = lane; i < cnt && i < MAXDEG; i += 32)
            sal[i] = expf(sl1[i] - m1) * r1 + expf(sl2[i] - m2) * r2;
        if (lane == 0) { st[0] = m1; st[1] = r1; st[2] = m2; st[3] = r2; }
    }
    __syncthreads();
    int c = tid;
    float acc = 0.f;
    float sd = g_s2d[n];
    for (int i = 0; i < cnt; i++) {
        float a;
        int s;
        if (i < MAXDEG) {
            s = se[i];
            a = sal[i];
        } else {
            s = g_esrc[p0 + i];
            float ev = g_s2s[s] + sd;
            a = expf(lrelu(ev) - st[0]) * st[1] + expf(lrelu(ev * g_mwq[p0 + i]) - st[2]) * st[3];
        }
        acc += a * g_h2w[s * OUTC + c];
    }
    out[n * OUTC + c] = out[n * OUTC + c] + acc + b2[c];
}

// ------------------------- launch --------------------------------------------
extern "C" void kernel_launch(void* const* d_in, const int* in_sizes, int n_in,
                              void* d_out, int out_size) {
    const float* x    = (const float*)d_in[0];
    const void*  ei   = d_in[1];
    const float* W1   = (const float*)d_in[2];
    const float* as1  = (const float*)d_in[3];
    const float* ad1  = (const float*)d_in[4];
    const float* b1   = (const float*)d_in[5];
    const float* W2   = (const float*)d_in[6];
    const float* as2  = (const float*)d_in[7];
    const float* ad2  = (const float*)d_in[8];
    const float* b2   = (const float*)d_in[9];
    const float* rW2  = (const float*)d_in[10];
    float* out = (float*)d_out;

    int E = in_sizes[1] / 2;
    int EP = E + NN;

    static cudaStream_t sC = 0;
    static cudaEvent_t ev0 = 0, evC = 0;
    if (!sC) {
        cudaStreamCreateWithFlags(&sC, cudaStreamNonBlocking);
        cudaEventCreateWithFlags(&ev0, cudaEventDisableTiming);
        cudaEventCreateWithFlags(&evC, cudaEventDisableTiming);
    }

    // fork
    cudaEventRecord(ev0, 0);
    cudaStreamWaitEvent(sC, ev0, 0);

    // branch C: operand splits -> gemm1 -> s1
    {
        int tot = NX8 + NW18 + 2 * NW28;
        k_splitall<<<(tot + 255) / 256, 256, 0, sC>>>(x, W1, W2, rW2);
        k_gemm1<<<dim3(INC / 128, NN / 128), 256, 0, sC>>>();
        k_s1<<<NN, 256, 0, sC>>>(as1, ad1);
        cudaEventRecord(evC, sC);
    }

    // main chain
    k_convert<<<(EP + 255) / 256, 256>>>(ei, E);
    k_deg<<<16, 256>>>();
    k_dualscan<<<1, 1024>>>();
    k_build<<<16 + (EP + 255) / 256, 256>>>(E);
    k_a2<<<NN, 256>>>();
    k_mw<<<(EP + 255) / 256, 256>>>(E);

    cudaStreamWaitEvent(0, evC, 0);
    k_sma1<<<NN, 256>>>(b1, E);
    k_gemm23<<<dim3(4, NN / 128), 256>>>(out, as2, ad2);
    k_sma2<<<NN + 64, 256>>>(b2, out, E);
}

// round 16
// speedup vs baseline: 1.0773x; 1.0773x over previous
#include <cuda_runtime.h>
#include <cuda_bf16.h>
#include <stdint.h>
#include <math.h>

#define NN 4096
#define EE_MAX 131072
#define EPMAX (EE_MAX + NN)
#define INC 512
#define NHEADS 8
#define HID 64
#define OUTC 256
#define WORDS (NN / 32)
#define NEG 0.2f
#define MAXDEG 384

// ------------------------- device scratch (static, no allocs) ---------------
__device__ int g_src[EE_MAX], g_dst[EE_MAX];
__device__ __align__(16) unsigned g_adj[NN * WORDS];    // zero at load; re-zeroed by sma2 tail
__device__ __align__(16) unsigned g_adjT[NN * WORDS];   // transpose bitmap, same lifecycle
__device__ int g_deg[NN], g_indeg[NN];
__device__ int g_rowptr[NN + 1];
__device__ int g_tptr[NN + 1];
__device__ int g_cols[EPMAX];
__device__ int g_tcols[EPMAX];
__device__ float g_d1[NN], g_d2[NN], g_d3[NN];
__device__ __align__(16) unsigned short g_A2h[NN * NN];   // 32 MB A2-TRANSPOSED (u16): row d = A2[:,d]
__device__ float g_h1[NN * INC];
__device__ float g_h2w[NN * OUTC];
__device__ float g_s1s[NN * NHEADS], g_s1d[NN * NHEADS];
__device__ float g_s2s[NN], g_s2d[NN];   // accumulated by gemm23 epilogue; zeroed in triscan
__device__ __align__(16) int g_hist[NN]; // zero at load; re-zeroed by sma2 tail
__device__ int g_dptr[NN + 1];
__device__ int g_dcur[NN];
__device__ int g_esrc[EPMAX];            // src node per CSR position (coalesced)
__device__ int g_edst[EPMAX];            // dst node per CSR position
__device__ float g_mwq[EPMAX];           // motif weight per CSR position (coalesced)

// bf16 split operands (hi + lo)
__device__ __align__(16) __nv_bfloat16 g_xhi[NN * INC], g_xlo[NN * INC];
__device__ __align__(16) __nv_bfloat16 g_w1hi[INC * INC], g_w1lo[INC * INC];
__device__ __align__(16) __nv_bfloat16 g_w2hi[INC * OUTC], g_w2lo[INC * OUTC];
__device__ __align__(16) __nv_bfloat16 g_rwhi[INC * OUTC], g_rwlo[INC * OUTC];
__device__ __align__(16) __nv_bfloat16 g_h2hi[NN * INC], g_h2lo[NN * INC];

// ------------------ convert + bitmaps + hist (pre-zeroed) --------------------
__global__ void k_convert(const void* p, int E) {
    __shared__ int any;
    if (threadIdx.x == 0) any = 0;
    __syncthreads();
    const int* w = (const int*)p;
#pragma unroll
    for (int t = 0; t < 4; t++) {
        int idx = threadIdx.x + t * 256;
        if (w[2 * idx + 1] != 0) any = 1;
    }
    __syncthreads();
    bool is64 = (any == 0);
    int i = blockIdx.x * blockDim.x + threadIdx.x;
    int EP = E + NN;
    if (i >= EP) return;
    int s, d;
    if (i < E) {
        if (is64) {
            const long long* q = (const long long*)p;
            s = (int)q[i];
            d = (int)q[E + i];
        } else {
            const int* q = (const int*)p;
            s = q[i];
            d = q[E + i];
        }
        g_src[i] = s;
        g_dst[i] = d;
    } else {
        s = i - E;
        d = i - E;
    }
    atomicOr(&g_adj[s * WORDS + (d >> 5)], 1u << (d & 31));
    atomicOr(&g_adjT[d * WORDS + (s >> 5)], 1u << (s & 31));
    atomicAdd(&g_hist[d], 1);
}

// ------------------------- fp32 -> (hi,lo) bf16 split ------------------------
__device__ __forceinline__ void split8(const float* __restrict__ src,
                                       __nv_bfloat16* __restrict__ hi,
                                       __nv_bfloat16* __restrict__ lo, int i) {
    const float4* s4 = (const float4*)src;
    float4 v0 = s4[2 * i], v1 = s4[2 * i + 1];
    float f[8] = {v0.x, v0.y, v0.z, v0.w, v1.x, v1.y, v1.z, v1.w};
    __nv_bfloat16 h[8], l[8];
#pragma unroll
    for (int k = 0; k < 8; k++) {
        h[k] = __float2bfloat16(f[k]);
        l[k] = __float2bfloat16(f[k] - __bfloat162float(h[k]));
    }
    ((uint4*)hi)[i] = *(uint4*)h;
    ((uint4*)lo)[i] = *(uint4*)l;
}

#define NX8 (NN * INC / 8)
#define NW18 (INC * INC / 8)
#define NW28 (INC * OUTC / 8)
__global__ void k_splitall(const float* __restrict__ x, const float* __restrict__ W1,
                           const float* __restrict__ W2, const float* __restrict__ rW2) {
    int i = blockIdx.x * blockDim.x + threadIdx.x;
    if (i < NX8) { split8(x, g_xhi, g_xlo, i); return; }
    i -= NX8;
    if (i < NW18) { split8(W1, g_w1hi, g_w1lo, i); return; }
    i -= NW18;
    if (i < NW28) { split8(W2, g_w2hi, g_w2lo, i); return; }
    i -= NW28;
    if (i < NW28) { split8(rW2, g_rwhi, g_rwlo, i); return; }
}

// ------------------------- degrees (fwd + transpose) -------------------------
__global__ void k_deg() {
    int r = blockIdx.x * blockDim.x + threadIdx.x;
    if (r < NN) {
        const uint4* row = (const uint4*)(g_adj + r * WORDS);
        int c = 0;
#pragma unroll
        for (int w = 0; w < WORDS / 4; w++) {
            uint4 v = row[w];
            c += __popc(v.x) + __popc(v.y) + __popc(v.z) + __popc(v.w);
        }
        g_deg[r] = c;
        g_d1[r] = (float)c;
    } else if (r < 2 * NN) {
        int t = r - NN;
        const uint4* row = (const uint4*)(g_adjT + t * WORDS);
        int c = 0;
#pragma unroll
        for (int w = 0; w < WORDS / 4; w++) {
            uint4 v = row[w];
            c += __popc(v.x) + __popc(v.y) + __popc(v.z) + __popc(v.w);
        }
        g_indeg[t] = c;
    }
}

// three scans: deg->rowptr, indeg->tptr, hist->dptr(+dcur); zero s2 accums
__global__ void k_triscan() {
    __shared__ int s[1024];
    int tid = threadIdx.x;
#pragma unroll
    for (int pass = 0; pass < 3; pass++) {
        const int* in = (pass == 0) ? g_deg : (pass == 1) ? g_indeg : g_hist;
        int* out = (pass == 0) ? g_rowptr : (pass == 1) ? g_tptr : g_dptr;
        int base = tid * 4;
        int loc[4];
        int tot = 0;
#pragma unroll
        for (int i = 0; i < 4; i++) { loc[i] = tot; tot += in[base + i]; }
        s[tid] = tot;
        __syncthreads();
        for (int off = 1; off < 1024; off <<= 1) {
            int t = (tid >= off) ? s[tid - off] : 0;
            __syncthreads();
            s[tid] += t;
            __syncthreads();
        }
        int pre = (tid == 0) ? 0 : s[tid - 1];
#pragma unroll
        for (int i = 0; i < 4; i++) {
            out[base + i] = pre + loc[i];
            if (pass == 2) g_dcur[base + i] = pre + loc[i];
        }
        if (tid == 1023) out[4096] = s[1023];
        __syncthreads();
    }
    int b4 = tid * 4;
#pragma unroll
    for (int i = 0; i < 4; i++) {
        g_s2s[b4 + i] = 0.f;
        g_s2d[b4 + i] = 0.f;
    }
}

// blocks 0-15: fwd fillcols + d2 ; 16-31: transpose fillcols ; 32+: scatter
__global__ void k_build(int E) {
    int EP = E + NN;
    if (blockIdx.x < 16) {
        int r = blockIdx.x * blockDim.x + threadIdx.x;
        if (r >= NN) return;
        int p = g_rowptr[r];
        float d2 = 0.f;
        for (int w = 0; w < WORDS; w++) {
            unsigned m = g_adj[r * WORDS + w];
            while (m) {
                int b = __ffs(m) - 1;
                int c = w * 32 + b;
                g_cols[p++] = c;
                d2 += g_d1[c];
                m &= m - 1;
            }
        }
        g_d2[r] = d2;
    } else if (blockIdx.x < 32) {
        int r = (blockIdx.x - 16) * blockDim.x + threadIdx.x;
        if (r >= NN) return;
        int p = g_tptr[r];
        for (int w = 0; w < WORDS; w++) {
            unsigned m = g_adjT[r * WORDS + w];
            while (m) {
                int b = __ffs(m) - 1;
                g_tcols[p++] = w * 32 + b;
                m &= m - 1;
            }
        }
    } else {
        int e = (blockIdx.x - 32) * blockDim.x + threadIdx.x;
        if (e >= EP) return;
        int s, d;
        if (e < E) { s = g_src[e]; d = g_dst[e]; }
        else { s = e - E; d = e - E; }
        int pos = atomicAdd(&g_dcur[d], 1);
        g_esrc[pos] = s;
        g_edst[pos] = d;
    }
}

// ---- block d: A2T row d in smem (paths k->m->d) + d3[d] ---------------------
__global__ void __launch_bounds__(256) k_a2() {
    __shared__ unsigned short row[NN];
    int tid = threadIdx.x;
    unsigned* roww = (unsigned*)row;
    for (int i = tid; i < NN / 2; i += 256) roww[i] = 0u;
    __syncthreads();
    int d = blockIdx.x;
    // d3[d] = sum_{c in adj(d)} d2[c]  (forward CSR row d)
    int f0 = g_rowptr[d], f1 = g_rowptr[d + 1];
    float d3 = 0.f;
    for (int i = f0 + tid; i < f1; i += 256) d3 += g_d2[g_cols[i]];
    for (int o = 16; o; o >>= 1) d3 += __shfl_xor_sync(0xffffffffu, d3, o);
    __shared__ float sred[8];
    if ((tid & 31) == 0) sred[tid >> 5] = d3;
    // A2T[d][k] += 1 for each m in in(d), k in in(m)
    int wid = tid >> 5, lane = tid & 31;
    int t0 = g_tptr[d], t1 = g_tptr[d + 1];
    for (int mi = t0 + wid; mi < t1; mi += 8) {
        int m = g_tcols[mi];
        int q1 = g_tptr[m + 1];
        for (int j = g_tptr[m] + lane; j < q1; j += 32) {
            int k = g_tcols[j];
            atomicAdd(&roww[k >> 1], (k & 1) ? 0x10000u : 1u);
        }
    }
    __syncthreads();
    if (tid == 0) {
        float t = 0.f;
        for (int i = 0; i < 8; i++) t += sred[i];
        g_d3[d] = t;
    }
    uint4* dst = (uint4*)(g_A2h + (size_t)d * NN);
    const uint4* srcv = (const uint4*)row;
    for (int i = tid; i < NN / 8; i += 256) dst[i] = srcv[i];
}

// mw per CSR position: warp-mates share d -> all gathers in one 8KB row (L1)
__global__ void k_mw(int E) {
    int pos = blockIdx.x * blockDim.x + threadIdx.x;
    int EP = E + NN;
    if (pos >= EP) return;
    int s = g_esrc[pos];
    int d = g_edst[pos];
    const unsigned short* rowT = g_A2h + (size_t)d * NN;
    float a3 = 0.f;
    int p1 = g_rowptr[s + 1];
    for (int i = g_rowptr[s]; i < p1; i++)
        a3 += (float)rowT[g_cols[i]];
    float nm = g_d3[s];
    if (nm < 1.f) nm = 1.f;
    g_mwq[pos] = a3 / nm;
}

// ------------------------- split-bf16 HMMA GEMM ------------------------------
#define PAD_A 40
#define PITCH_B 136

__device__ __forceinline__ void mma_bf16(float* c, const unsigned* a, const unsigned* b) {
    asm volatile(
        "mma.sync.aligned.m16n8k16.row.col.f32.bf16.bf16.f32 "
        "{%0,%1,%2,%3}, {%4,%5,%6,%7}, {%8,%9}, {%0,%1,%2,%3};"
        : "+f"(c[0]), "+f"(c[1]), "+f"(c[2]), "+f"(c[3])
        : "r"(a[0]), "r"(a[1]), "r"(a[2]), "r"(a[3]), "r"(b[0]), "r"(b[1]));
}

template <bool FUSE_S2>
__device__ __forceinline__ void gemm_split(const __nv_bfloat16* __restrict__ Ahi,
                                           const __nv_bfloat16* __restrict__ Alo,
                                           const __nv_bfloat16* __restrict__ Bhi,
                                           const __nv_bfloat16* __restrict__ Blo,
                                           int ldb, int col0,
                                           float* __restrict__ C, int ldc, int row0,
                                           const float* __restrict__ av,
                                           const float* __restrict__ dv) {
    __shared__ __nv_bfloat16 As[2][128 * PAD_A];
    __shared__ __nv_bfloat16 Bs[2][32 * PITCH_B];
    int tid = threadIdx.x;
    int wid = tid >> 5, lane = tid & 31;
    int wm = (wid >> 2) * 64;
    int wn = (wid & 3) * 32;
    int g = lane >> 2, q = lane & 3;
    float acc[4][4][4] = {};

    for (int k0 = 0; k0 < INC; k0 += 32) {
#pragma unroll
        for (int l = 0; l < 2; l++) {
            int slot = tid + l * 256;
            int r = slot >> 2, cg = (slot & 3) << 3;
            *(float4*)&As[0][r * PAD_A + cg] = *(const float4*)&Ahi[(row0 + r) * INC + k0 + cg];
            *(float4*)&As[1][r * PAD_A + cg] = *(const float4*)&Alo[(row0 + r) * INC + k0 + cg];
        }
#pragma unroll
        for (int l = 0; l < 2; l++) {
            int slot = tid + l * 256;
            int kr = slot >> 4, ng = (slot & 15) << 3;
            *(float4*)&Bs[0][kr * PITCH_B + ng] = *(const float4*)&Bhi[(k0 + kr) * ldb + col0 + ng];
            *(float4*)&Bs[1][kr * PITCH_B + ng] = *(const float4*)&Blo[(k0 + kr) * ldb + col0 + ng];
        }
        __syncthreads();
#pragma unroll
        for (int ks = 0; ks < 2; ks++) {
            int kb = ks * 16;
            unsigned ah[4][4], al[4][4], bh[4][2], bl[4][2];
#pragma unroll
            for (int i = 0; i < 4; i++) {
                int m = wm + i * 16 + g;
                int o0 = m * PAD_A + kb + q * 2;
                int o1 = (m + 8) * PAD_A + kb + q * 2;
                ah[i][0] = *(const unsigned*)&As[0][o0];
                ah[i][1] = *(const unsigned*)&As[0][o1];
                ah[i][2] = *(const unsigned*)&As[0][o0 + 8];
                ah[i][3] = *(const unsigned*)&As[0][o1 + 8];
                al[i][0] = *(const unsigned*)&As[1][o0];
                al[i][1] = *(const unsigned*)&As[1][o1];
                al[i][2] = *(const unsigned*)&As[1][o0 + 8];
                al[i][3] = *(const unsigned*)&As[1][o1 + 8];
            }
#pragma unroll
            for (int j = 0; j < 4; j++) {
                int n = wn + j * 8 + g;
                int k2 = kb + q * 2;
#pragma unroll
                for (int t = 0; t < 2; t++) {
                    int kk = k2 + t * 8;
                    unsigned h0 = *(const unsigned short*)&Bs[0][kk * PITCH_B + n];
                    unsigned h1 = *(const unsigned short*)&Bs[0][(kk + 1) * PITCH_B + n];
                    bh[j][t] = h0 | (h1 << 16);
                    unsigned l0 = *(const unsigned short*)&Bs[1][kk * PITCH_B + n];
                    unsigned l1 = *(const unsigned short*)&Bs[1][(kk + 1) * PITCH_B + n];
                    bl[j][t] = l0 | (l1 << 16);
                }
            }
#pragma unroll
            for (int i = 0; i < 4; i++)
#pragma unroll
                for (int j = 0; j < 4; j++) {
                    mma_bf16(acc[i][j], ah[i], bh[j]);
                    mma_bf16(acc[i][j], ah[i], bl[j]);
                    mma_bf16(acc[i][j], al[i], bh[j]);
                }
        }
        __syncthreads();
    }
#pragma unroll
    for (int i = 0; i < 4; i++)
#pragma unroll
        for (int j = 0; j < 4; j++) {
            int r = row0 + wm + i * 16 + g;
            int c = col0 + wn + j * 8 + q * 2;
            C[r * ldc + c] = acc[i][j][0];
            C[r * ldc + c + 1] = acc[i][j][1];
            C[(r + 8) * ldc + c] = acc[i][j][2];
            C[(r + 8) * ldc + c + 1] = acc[i][j][3];
        }
    if (FUSE_S2) {
#pragma unroll
        for (int i = 0; i < 4; i++) {
            float s0 = 0.f, d0 = 0.f, s8 = 0.f, d8 = 0.f;
#pragma unroll
            for (int j = 0; j < 4; j++) {
                int c = col0 + wn + j * 8 + q * 2;
                float a0 = av[c], a1 = av[c + 1];
                float e0 = dv[c], e1 = dv[c + 1];
                s0 += acc[i][j][0] * a0 + acc[i][j][1] * a1;
                d0 += acc[i][j][0] * e0 + acc[i][j][1] * e1;
                s8 += acc[i][j][2] * a0 + acc[i][j][3] * a1;
                d8 += acc[i][j][2] * e0 + acc[i][j][3] * e1;
            }
            s0 += __shfl_xor_sync(0xffffffffu, s0, 1);
            s0 += __shfl_xor_sync(0xffffffffu, s0, 2);
            d0 += __shfl_xor_sync(0xffffffffu, d0, 1);
            d0 += __shfl_xor_sync(0xffffffffu, d0, 2);
            s8 += __shfl_xor_sync(0xffffffffu, s8, 1);
            s8 += __shfl_xor_sync(0xffffffffu, s8, 2);
            d8 += __shfl_xor_sync(0xffffffffu, d8, 1);
            d8 += __shfl_xor_sync(0xffffffffu, d8, 2);
            if (q == 0) {
                int r = row0 + wm + i * 16 + g;
                atomicAdd(&g_s2s[r], s0);
                atomicAdd(&g_s2d[r], d0);
                atomicAdd(&g_s2s[r + 8], s8);
                atomicAdd(&g_s2d[r + 8], d8);
            }
        }
    }
}

__global__ void __launch_bounds__(256) k_gemm1() {
    gemm_split<false>(g_xhi, g_xlo, g_w1hi, g_w1lo, INC, blockIdx.x * 128, g_h1, INC,
                      blockIdx.y * 128, 0, 0);
}

__global__ void __launch_bounds__(256) k_gemm23(float* __restrict__ out,
                                                const float* __restrict__ as2,
                                                const float* __restrict__ ad2) {
    int bx = blockIdx.x;
    if (bx < 2) {
        gemm_split<true>(g_h2hi, g_h2lo, g_w2hi, g_w2lo, OUTC, (bx & 1) * 128,
                         g_h2w, OUTC, blockIdx.y * 128, as2, ad2);
    } else {
        gemm_split<false>(g_h2hi, g_h2lo, g_rwhi, g_rwlo, OUTC, (bx & 1) * 128,
                          out, OUTC, blockIdx.y * 128, 0, 0);
    }
}

// ------------------- attention scores (layer 1) ------------------------------
__global__ void k_s1(const float* __restrict__ as1, const float* __restrict__ ad1) {
    int n = blockIdx.x;
    int h = threadIdx.x >> 5, lane = threadIdx.x & 31;
    float2 v = *(const float2*)&g_h1[n * INC + h * HID + lane * 2];
    float2 a = *(const float2*)&as1[h * HID + lane * 2];
    float2 d = *(const float2*)&ad1[h * HID + lane * 2];
    float ss = v.x * a.x + v.y * a.y;
    float sd = v.x * d.x + v.y * d.y;
    for (int o = 16; o; o >>= 1) {
        ss += __shfl_xor_sync(0xffffffffu, ss, o);
        sd += __shfl_xor_sync(0xffffffffu, sd, o);
    }
    if (lane == 0) {
        g_s1s[n * NHEADS + h] = ss;
        g_s1d[n * NHEADS + h] = sd;
    }
}

// ------------------- fused softmax + aggregate + split, layer 1 --------------
__device__ __forceinline__ float lrelu(float x) { return x > 0.f ? x : NEG * x; }

__global__ void __launch_bounds__(256) k_sma1(const float* __restrict__ b1, int E) {
    __shared__ float sal[MAXDEG * NHEADS];
    __shared__ int se[MAXDEG];
    __shared__ float sm1[NHEADS], sr1[NHEADS], sm2[NHEADS], sr2[NHEADS];
    int n = blockIdx.x;
    int p0 = g_dptr[n], p1 = g_dptr[n + 1];
    int cnt = p1 - p0;
    int tid = threadIdx.x, h = tid >> 5, lane = tid & 31;
    float sd = g_s1d[n * NHEADS + h];
    float m1 = -1e30f, m2 = -1e30f;
    for (int i = lane; i < cnt; i += 32) {
        int s = g_esrc[p0 + i];
        if (h == 0 && i < MAXDEG) se[i] = s;
        float ev = g_s1s[s * NHEADS + h] + sd;
        m1 = fmaxf(m1, lrelu(ev));
        m2 = fmaxf(m2, lrelu(ev * g_mwq[p0 + i]));
    }
    for (int o = 16; o; o >>= 1) {
        m1 = fmaxf(m1, __shfl_xor_sync(0xffffffffu, m1, o));
        m2 = fmaxf(m2, __shfl_xor_sync(0xffffffffu, m2, o));
    }
    float s1 = 0.f, s2 = 0.f;
    for (int i = lane; i < cnt; i += 32) {
        int s = g_esrc[p0 + i];
        float ev = g_s1s[s * NHEADS + h] + sd;
        s1 += expf(lrelu(ev) - m1);
        s2 += expf(lrelu(ev * g_mwq[p0 + i]) - m2);
    }
    for (int o = 16; o; o >>= 1) {
        s1 += __shfl_xor_sync(0xffffffffu, s1, o);
        s2 += __shfl_xor_sync(0xffffffffu, s2, o);
    }
    float r1 = 0.5f / (s1 + 1e-16f);
    float r2 = 0.5f / (s2 + 1e-16f);
    for (int i = lane; i < cnt && i < MAXDEG; i += 32) {
        int s = g_esrc[p0 + i];
        float ev = g_s1s[s * NHEADS + h] + sd;
        sal[i * NHEADS + h] = expf(lrelu(ev) - m1) * r1
                            + expf(lrelu(ev * g_mwq[p0 + i]) - m2) * r2;
    }
    if (lane == 0) { sm1[h] = m1; sr1[h] = r1; sm2[h] = m2; sr2[h] = r2; }
    __syncthreads();
    int c = h * HID + lane * 2;
    float2 acc = make_float2(0.f, 0.f);
    for (int i = 0; i < cnt; i++) {
        float a;
        int s;
        if (i < MAXDEG) {
            s = se[i];
            a = sal[i * NHEADS + h];
        } else {
            s = g_esrc[p0 + i];
            float ev = g_s1s[s * NHEADS + h] + sd;
            a = expf(lrelu(ev) - sm1[h]) * sr1[h]
              + expf(lrelu(ev * g_mwq[p0 + i]) - sm2[h]) * sr2[h];
        }
        float2 v = *(const float2*)&g_h1[s * INC + c];
        acc.x += a * v.x;
        acc.y += a * v.y;
    }
    float2 bb = *(const float2*)&b1[c];
    float rx = acc.x + bb.x, ry = acc.y + bb.y;
    rx = rx > 0.f ? rx : expm1f(rx);
    ry = ry > 0.f ? ry : expm1f(ry);
    __nv_bfloat16 hx = __float2bfloat16(rx);
    __nv_bfloat16 hy = __float2bfloat16(ry);
    __nv_bfloat16 lx = __float2bfloat16(rx - __bfloat162float(hx));
    __nv_bfloat16 ly = __float2bfloat16(ry - __bfloat162float(hy));
    __nv_bfloat162 hp; hp.x = hx; hp.y = hy;
    __nv_bfloat162 lp; lp.x = lx; lp.y = ly;
    *(__nv_bfloat162*)&g_h2hi[n * INC + c] = hp;
    *(__nv_bfloat162*)&g_h2lo[n * INC + c] = lp;
}

// ------------- fused softmax + aggregate, layer 2 (+ tail cleanup) -----------
__global__ void __launch_bounds__(256) k_sma2(const float* __restrict__ b2,
                                              float* __restrict__ out, int E) {
    int n = blockIdx.x;
    if (n >= NN) {   // cleanup blocks: re-zero adj/adjT/hist for the next launch
        int idx = (n - NN) * 256 + threadIdx.x;
        uint4 zu = make_uint4(0u, 0u, 0u, 0u);
        uint4* adjv = (uint4*)g_adj;
        uint4* adjtv = (uint4*)g_adjT;
        for (int i = idx; i < NN * WORDS / 4; i += 64 * 256) {
            adjv[i] = zu;
            adjtv[i] = zu;
        }
        uint4* hv = (uint4*)g_hist;
        for (int i = idx; i < NN / 4; i += 64 * 256) hv[i] = zu;
        return;
    }
    __shared__ float sal[MAXDEG];
    __shared__ int se[MAXDEG];
    __shared__ float st[4];
    int p0 = g_dptr[n], p1 = g_dptr[n + 1];
    int cnt = p1 - p0;
    int tid = threadIdx.x;
    if (tid < 32) {
        int lane = tid;
        float sd = g_s2d[n];
        float m1 = -1e30f, m2 = -1e30f;
        for (int i = lane; i < cnt; i += 32) {
            int s = g_esrc[p0 + i];
            if (i < MAXDEG) se[i] = s;
            float ev = g_s2s[s] + sd;
            m1 = fmaxf(m1, lrelu(ev));
            m2 = fmaxf(m2, lrelu(ev * g_mwq[p0 + i]));
        }
        for (int o = 16; o; o >>= 1) {
            m1 = fmaxf(m1, __shfl_xor_sync(0xffffffffu, m1, o));
            m2 = fmaxf(m2, __shfl_xor_sync(0xffffffffu, m2, o));
        }
        float s1 = 0.f, s2 = 0.f;
        for (int i = lane; i < cnt; i += 32) {
            int s = g_esrc[p0 + i];
            float ev = g_s2s[s] + sd;
            s1 += expf(lrelu(ev) - m1);
            s2 += expf(lrelu(ev * g_mwq[p0 + i]) - m2);
        }
        for (int o = 16; o; o >>= 1) {
            s1 += __shfl_xor_sync(0xffffffffu, s1, o);
            s2 += __shfl_xor_sync(0xffffffffu, s2, o);
        }
        float r1 = 0.5f / (s1 + 1e-16f);
        float r2 = 0.5f / (s2 + 1e-16f);
        for (int i = lane; i < cnt && i < MAXDEG; i += 32) {
            int s = g_esrc[p0 + i];
            float ev = g_s2s[s] + sd;
            sal[i] = expf(lrelu(ev) - m1) * r1 + expf(lrelu(ev * g_mwq[p0 + i]) - m2) * r2;
        }
        if (lane == 0) { st[0] = m1; st[1] = r1; st[2] = m2; st[3] = r2; }
    }
    __syncthreads();
    int c = tid;
    float acc = 0.f;
    float sd = g_s2d[n];
    for (int i = 0; i < cnt; i++) {
        float a;
        int s;
        if (i < MAXDEG) {
            s = se[i];
            a = sal[i];
        } else {
            s = g_esrc[p0 + i];
            float ev = g_s2s[s] + sd;
            a = expf(lrelu(ev) - st[0]) * st[1] + expf(lrelu(ev * g_mwq[p0 + i]) - st[2]) * st[3];
        }
        acc += a * g_h2w[s * OUTC + c];
    }
    out[n * OUTC + c] = out[n * OUTC + c] + acc + b2[c];
}

// ------------------------- launch --------------------------------------------
extern "C" void kernel_launch(void* const* d_in, const int* in_sizes, int n_in,
                              void* d_out, int out_size) {
    const float* x    = (const float*)d_in[0];
    const void*  ei   = d_in[1];
    const float* W1   = (const float*)d_in[2];
    const float* as1  = (const float*)d_in[3];
    const float* ad1  = (const float*)d_in[4];
    const float* b1   = (const float*)d_in[5];
    const float* W2   = (const float*)d_in[6];
    const float* as2  = (const float*)d_in[7];
    const float* ad2  = (const float*)d_in[8];
    const float* b2   = (const float*)d_in[9];
    const float* rW2  = (const float*)d_in[10];
    float* out = (float*)d_out;

    int E = in_sizes[1] / 2;
    int EP = E + NN;

    static cudaStream_t sC = 0;
    static cudaEvent_t ev0 = 0, evC = 0;
    if (!sC) {
        cudaStreamCreateWithFlags(&sC, cudaStreamNonBlocking);
        cudaEventCreateWithFlags(&ev0, cudaEventDisableTiming);
        cudaEventCreateWithFlags(&evC, cudaEventDisableTiming);
    }

    // fork
    cudaEventRecord(ev0, 0);
    cudaStreamWaitEvent(sC, ev0, 0);

    // branch C: operand splits -> gemm1 -> s1
    {
        int tot = NX8 + NW18 + 2 * NW28;
        k_splitall<<<(tot + 255) / 256, 256, 0, sC>>>(x, W1, W2, rW2);
        k_gemm1<<<dim3(INC / 128, NN / 128), 256, 0, sC>>>();
        k_s1<<<NN, 256, 0, sC>>>(as1, ad1);
        cudaEventRecord(evC, sC);
    }

    // main chain
    k_convert<<<(EP + 255) / 256, 256>>>(ei, E);
    k_deg<<<32, 256>>>();
    k_triscan<<<1, 1024>>>();
    k_build<<<32 + (EP + 255) / 256, 256>>>(E);
    k_a2<<<NN, 256>>>();
    k_mw<<<(EP + 255) / 256, 256>>>(E);

    cudaStreamWaitEvent(0, evC, 0);
    k_sma1<<<NN, 256>>>(b1, E);
    k_gemm23<<<dim3(4, NN / 128), 256>>>(out, as2, ad2);
    k_sma2<<<NN + 64, 256>>>(b2, out, E);
}